// round 1
// baseline (speedup 1.0000x reference)
#include <cuda_runtime.h>
#include <math.h>

#define BATCH 4
#define SEQ   1024
#define DIM   512
#define NH    8
#define DHD   64
#define R2    2047   // 2*SEQ-1

// ---------------- scratch (static device memory; no allocs) ----------------
__device__ float g_q[BATCH*SEQ*DIM];
__device__ float g_k[BATCH*SEQ*DIM];
__device__ float g_v[BATCH*SEQ*DIM];
__device__ float g_pe[R2*DIM];
__device__ float g_E[R2*DIM];
__device__ float g_att[BATCH*SEQ*DIM];

// ---------------- relative sinusoidal PE ----------------
// pe[i, 2j] = sin(pos_i * f_j), pe[i, 2j+1] = cos(...), pos_i = SEQ-1-i,
// f_j = 10000^(-j/256). Match reference's f32 rounding of pos*f, then
// evaluate sin/cos in double.
__global__ void pe_kernel(float* __restrict__ pe) {
    int i = blockIdx.x;           // 0..2046
    int j = threadIdx.x;          // 0..255
    float pos  = (float)(SEQ - 1 - i);
    float invf = (float)exp(-(double)j * (log(10000.0) / 256.0));
    float ang  = pos * invf;
    double s, c;
    sincos((double)ang, &s, &c);
    pe[(size_t)i*DIM + 2*j]     = (float)s;
    pe[(size_t)i*DIM + 2*j + 1] = (float)c;
}

// ---------------- C = A @ W^T + bias  (K = N = 512) ----------------
// NT gemm, both operands row-major contiguous along k. 128x128x16 tile,
// 256 threads, 8x8 microtile.
#define GBM 128
#define GBN 128
#define GBK 16

__global__ __launch_bounds__(256, 2)
void gemm_nt_bias(const float* __restrict__ A, const float* __restrict__ W,
                  const float* __restrict__ bias, float* __restrict__ C, int M) {
    __shared__ float sA[GBK][GBM + 4];
    __shared__ float sB[GBK][GBN + 4];
    const int tid = threadIdx.x;
    const int tx  = tid & 15;
    const int ty  = tid >> 4;
    const int m0  = blockIdx.y * GBM;
    const int n0  = blockIdx.x * GBN;
    const int lr  = tid >> 2;          // 0..63
    const int lc  = (tid & 3) * 4;     // 0,4,8,12

    float acc[8][8];
    #pragma unroll
    for (int i = 0; i < 8; i++)
        #pragma unroll
        for (int j = 0; j < 8; j++) acc[i][j] = 0.f;

    for (int k0 = 0; k0 < DIM; k0 += GBK) {
        #pragma unroll
        for (int half = 0; half < 2; half++) {
            int mr = lr + half * 64;
            int m  = m0 + mr;
            float4 va = make_float4(0.f, 0.f, 0.f, 0.f);
            if (m < M) va = *(const float4*)(A + (size_t)m*DIM + k0 + lc);
            sA[lc+0][mr] = va.x; sA[lc+1][mr] = va.y;
            sA[lc+2][mr] = va.z; sA[lc+3][mr] = va.w;
            int n = n0 + mr;   // N = 512 always covered exactly
            float4 vb = *(const float4*)(W + (size_t)n*DIM + k0 + lc);
            sB[lc+0][mr] = vb.x; sB[lc+1][mr] = vb.y;
            sB[lc+2][mr] = vb.z; sB[lc+3][mr] = vb.w;
        }
        __syncthreads();
        #pragma unroll
        for (int kk = 0; kk < GBK; kk++) {
            float ra[8], rb[8];
            *(float4*)(ra)     = *(float4*)&sA[kk][ty*8];
            *(float4*)(ra + 4) = *(float4*)&sA[kk][ty*8 + 4];
            *(float4*)(rb)     = *(float4*)&sB[kk][tx*8];
            *(float4*)(rb + 4) = *(float4*)&sB[kk][tx*8 + 4];
            #pragma unroll
            for (int i = 0; i < 8; i++)
                #pragma unroll
                for (int j = 0; j < 8; j++)
                    acc[i][j] += ra[i] * rb[j];
        }
        __syncthreads();
    }
    #pragma unroll
    for (int i = 0; i < 8; i++) {
        int m = m0 + ty*8 + i;
        if (m >= M) continue;
        #pragma unroll
        for (int jv = 0; jv < 2; jv++) {
            int n = n0 + tx*8 + jv*4;
            float4 bb = *(const float4*)(bias + n);
            float4 o;
            o.x = acc[i][jv*4+0] + bb.x;
            o.y = acc[i][jv*4+1] + bb.y;
            o.z = acc[i][jv*4+2] + bb.z;
            o.w = acc[i][jv*4+3] + bb.w;
            *(float4*)(C + (size_t)m*DIM + n) = o;
        }
    }
}

// ---------------- fused rel-pos flash attention ----------------
// One block = one (b,h, 64-row q-tile). Loops 16 k-tiles of 64.
// S[qi,kj] = (Qu[qi].K[kj] + Qv[qi].E[kj-qi+63 band]) / 8, online softmax, O += P.V
#define ATTN_SMEM_FLOATS (5*64*68 + 2*64*132 + 4*64 + 64*16)
#define ATTN_SMEM_BYTES  (ATTN_SMEM_FLOATS * 4)

__global__ __launch_bounds__(256, 1)
void attn_kernel(const float* __restrict__ gq, const float* __restrict__ gk,
                 const float* __restrict__ gv, const float* __restrict__ gE,
                 const float* __restrict__ ub, const float* __restrict__ vb,
                 float* __restrict__ gatt) {
    extern __shared__ float sm[];
    float* sQuT = sm;                 // [64 d][68] (d-major)
    float* sQvT = sQuT + 64*68;       // [64 d][68]
    float* sKT  = sQvT + 64*68;       // [64 d][68]
    float* sV   = sKT  + 64*68;       // [64 kj][68] (row-major)
    float* sP   = sV   + 64*68;       // [64 qi][68]
    float* sEt  = sP   + 64*68;       // [64 d][132] (d-major, 128 band rows)
    float* sT2  = sEt  + 64*132;      // [64 qi][132]
    float* m_run    = sT2 + 64*132;   // [64]
    float* l_run    = m_run + 64;
    float* rowscale = l_run + 64;
    float* msub     = rowscale + 64;
    float* red      = msub + 64;      // [64][16]

    const int tid = threadIdx.x;
    const int tx  = tid & 15;
    const int ty  = tid >> 4;
    const int b   = blockIdx.y >> 3;
    const int h   = blockIdx.y & 7;
    const int q0  = blockIdx.x * 64;
    const size_t headoff = (size_t)h * DHD;

    // ---- load Qu/Qv (transposed into SMEM, bias fused) ----
    #pragma unroll
    for (int it = 0; it < 4; it++) {
        int idx = tid + it*256;
        int row = idx >> 4;
        int c4  = (idx & 15) * 4;
        float4 val = *(const float4*)(gq + ((size_t)(b*SEQ) + q0 + row)*DIM + headoff + c4);
        float4 u4  = *(const float4*)(ub + headoff + c4);
        float4 v4  = *(const float4*)(vb + headoff + c4);
        sQuT[(c4+0)*68+row] = val.x + u4.x;
        sQuT[(c4+1)*68+row] = val.y + u4.y;
        sQuT[(c4+2)*68+row] = val.z + u4.z;
        sQuT[(c4+3)*68+row] = val.w + u4.w;
        sQvT[(c4+0)*68+row] = val.x + v4.x;
        sQvT[(c4+1)*68+row] = val.y + v4.y;
        sQvT[(c4+2)*68+row] = val.z + v4.z;
        sQvT[(c4+3)*68+row] = val.w + v4.w;
    }
    if (tid < 64) { m_run[tid] = -INFINITY; l_run[tid] = 0.f; }
    float accO[4][4];
    #pragma unroll
    for (int i = 0; i < 4; i++)
        #pragma unroll
        for (int j = 0; j < 4; j++) accO[i][j] = 0.f;
    __syncthreads();

    for (int kt = 0; kt < 16; kt++) {
        const int k0 = kt * 64;
        // ---- load K (transposed), V (row-major) ----
        #pragma unroll
        for (int it = 0; it < 4; it++) {
            int idx = tid + it*256;
            int row = idx >> 4;
            int c4  = (idx & 15) * 4;
            float4 kvv = *(const float4*)(gk + ((size_t)(b*SEQ) + k0 + row)*DIM + headoff + c4);
            sKT[(c4+0)*68+row] = kvv.x; sKT[(c4+1)*68+row] = kvv.y;
            sKT[(c4+2)*68+row] = kvv.z; sKT[(c4+3)*68+row] = kvv.w;
            float4 vvv = *(const float4*)(gv + ((size_t)(b*SEQ) + k0 + row)*DIM + headoff + c4);
            *(float4*)&sV[row*68 + c4] = vvv;
        }
        // ---- load E band rows [rbase, rbase+126] (transposed), row 127 zero ----
        const int rbase = k0 - q0 + (SEQ - 64);
        #pragma unroll
        for (int it = 0; it < 8; it++) {
            int idx  = tid + it*256;
            int trow = idx >> 4;
            int c4   = (idx & 15) * 4;
            float4 ev = make_float4(0.f, 0.f, 0.f, 0.f);
            if (trow < 127)
                ev = *(const float4*)(gE + (size_t)(rbase + trow)*DIM + headoff + c4);
            sEt[(c4+0)*132+trow] = ev.x; sEt[(c4+1)*132+trow] = ev.y;
            sEt[(c4+2)*132+trow] = ev.z; sEt[(c4+3)*132+trow] = ev.w;
        }
        __syncthreads();

        // ---- T2 = Qv_tile @ E_band^T  (64 x 128) ----
        {
            float acc2[4][8];
            #pragma unroll
            for (int i = 0; i < 4; i++)
                #pragma unroll
                for (int j = 0; j < 8; j++) acc2[i][j] = 0.f;
            #pragma unroll 8
            for (int d = 0; d < 64; d++) {
                float a[4], e[8];
                *(float4*)a     = *(float4*)&sQvT[d*68 + ty*4];
                *(float4*)e     = *(float4*)&sEt[d*132 + tx*8];
                *(float4*)(e+4) = *(float4*)&sEt[d*132 + tx*8 + 4];
                #pragma unroll
                for (int i = 0; i < 4; i++)
                    #pragma unroll
                    for (int j = 0; j < 8; j++)
                        acc2[i][j] += a[i] * e[j];
            }
            #pragma unroll
            for (int i = 0; i < 4; i++) {
                *(float4*)&sT2[(ty*4+i)*132 + tx*8]     = *(float4*)&acc2[i][0];
                *(float4*)&sT2[(ty*4+i)*132 + tx*8 + 4] = *(float4*)&acc2[i][4];
            }
        }
        __syncthreads();

        // ---- S = Qu.K^T + shift(T2), scaled ----
        float S[4][4];
        {
            float acc1[4][4];
            #pragma unroll
            for (int i = 0; i < 4; i++)
                #pragma unroll
                for (int j = 0; j < 4; j++) acc1[i][j] = 0.f;
            #pragma unroll 8
            for (int d = 0; d < 64; d++) {
                float a[4], kk_[4];
                *(float4*)a   = *(float4*)&sQuT[d*68 + ty*4];
                *(float4*)kk_ = *(float4*)&sKT[d*68 + tx*4];
                #pragma unroll
                for (int i = 0; i < 4; i++)
                    #pragma unroll
                    for (int j = 0; j < 4; j++)
                        acc1[i][j] += a[i] * kk_[j];
            }
            #pragma unroll
            for (int i = 0; i < 4; i++)
                #pragma unroll
                for (int j = 0; j < 4; j++) {
                    int t = (tx*4 + j) - (ty*4 + i) + 63;   // 0..126
                    S[i][j] = (acc1[i][j] + sT2[(ty*4+i)*132 + t]) * 0.125f;
                }
        }

        // ---- online softmax ----
        #pragma unroll
        for (int i = 0; i < 4; i++) {
            float pm = fmaxf(fmaxf(S[i][0], S[i][1]), fmaxf(S[i][2], S[i][3]));
            red[(ty*4+i)*16 + tx] = pm;
        }
        __syncthreads();
        if (tid < 64) {
            float tm = red[tid*16];
            #pragma unroll
            for (int c2 = 1; c2 < 16; c2++) tm = fmaxf(tm, red[tid*16 + c2]);
            float mold = m_run[tid];
            float mn   = fmaxf(mold, tm);
            float rs   = (mold == -INFINITY) ? 0.f : __expf(mold - mn);
            rowscale[tid] = rs;
            msub[tid]     = mn;
            m_run[tid]    = mn;
            l_run[tid]   *= rs;
        }
        __syncthreads();
        #pragma unroll
        for (int i = 0; i < 4; i++) {
            int row  = ty*4 + i;
            float mn = msub[row];
            float rs = rowscale[row];
            float ps = 0.f;
            #pragma unroll
            for (int j = 0; j < 4; j++) {
                float p = __expf(S[i][j] - mn);
                sP[row*68 + tx*4 + j] = p;
                ps += p;
                accO[i][j] *= rs;
            }
            red[row*16 + tx] = ps;
        }
        __syncthreads();
        if (tid < 64) {
            float ssum = 0.f;
            #pragma unroll
            for (int c2 = 0; c2 < 16; c2++) ssum += red[tid*16 + c2];
            l_run[tid] += ssum;
        }

        // ---- O += P @ V ----
        #pragma unroll 8
        for (int kj = 0; kj < 64; kj++) {
            float vv[4];
            *(float4*)vv = *(float4*)&sV[kj*68 + tx*4];
            #pragma unroll
            for (int i = 0; i < 4; i++) {
                float p = sP[(ty*4+i)*68 + kj];
                #pragma unroll
                for (int j = 0; j < 4; j++)
                    accO[i][j] += p * vv[j];
            }
        }
        __syncthreads();
    }

    // ---- normalize + store ----
    #pragma unroll
    for (int i = 0; i < 4; i++) {
        int row = ty*4 + i;
        float inv = 1.f / l_run[row];
        float4 o;
        o.x = accO[i][0]*inv; o.y = accO[i][1]*inv;
        o.z = accO[i][2]*inv; o.w = accO[i][3]*inv;
        *(float4*)(gatt + ((size_t)(b*SEQ) + q0 + row)*DIM + headoff + tx*4) = o;
    }
}

// ---------------- launcher ----------------
extern "C" void kernel_launch(void* const* d_in, const int* in_sizes, int n_in,
                              void* d_out, int out_size) {
    const float* query  = (const float*)d_in[0];
    const float* key_   = (const float*)d_in[1];
    const float* value  = (const float*)d_in[2];
    const float* Wq     = (const float*)d_in[3];
    const float* bq     = (const float*)d_in[4];
    const float* Wk     = (const float*)d_in[5];
    const float* bk     = (const float*)d_in[6];
    const float* Wv     = (const float*)d_in[7];
    const float* bv     = (const float*)d_in[8];
    const float* Wp     = (const float*)d_in[9];
    const float* bp     = (const float*)d_in[10];
    const float* Wo     = (const float*)d_in[11];
    const float* bo     = (const float*)d_in[12];
    const float* u_bias = (const float*)d_in[13];
    const float* v_bias = (const float*)d_in[14];
    float* out = (float*)d_out;

    float *pq, *pk, *pv, *ppe, *pE, *patt;
    cudaGetSymbolAddress((void**)&pq,   g_q);
    cudaGetSymbolAddress((void**)&pk,   g_k);
    cudaGetSymbolAddress((void**)&pv,   g_v);
    cudaGetSymbolAddress((void**)&ppe,  g_pe);
    cudaGetSymbolAddress((void**)&pE,   g_E);
    cudaGetSymbolAddress((void**)&patt, g_att);

    cudaFuncSetAttribute(attn_kernel, cudaFuncAttributeMaxDynamicSharedMemorySize,
                         ATTN_SMEM_BYTES);

    pe_kernel<<<R2, 256>>>(ppe);
    gemm_nt_bias<<<dim3(4, 32), 256>>>(query, Wq, bq, pq, BATCH*SEQ);
    gemm_nt_bias<<<dim3(4, 32), 256>>>(key_,  Wk, bk, pk, BATCH*SEQ);
    gemm_nt_bias<<<dim3(4, 32), 256>>>(value, Wv, bv, pv, BATCH*SEQ);
    gemm_nt_bias<<<dim3(4, 16), 256>>>(ppe,   Wp, bp, pE, R2);
    attn_kernel<<<dim3(16, 32), 256, ATTN_SMEM_BYTES>>>(pq, pk, pv, pE,
                                                        u_bias, v_bias, patt);
    gemm_nt_bias<<<dim3(4, 32), 256>>>(patt, Wo, bo, out, BATCH*SEQ);
}

// round 2
// speedup vs baseline: 1.1941x; 1.1941x over previous
#include <cuda_runtime.h>
#include <math.h>

#define BATCH 4
#define SEQ   1024
#define DIM   512
#define NH    8
#define DHD   64
#define R2    2047   // 2*SEQ-1

// ---------------- scratch (static device memory; no allocs) ----------------
__device__ float g_q[BATCH*SEQ*DIM];
__device__ float g_k[BATCH*SEQ*DIM];
__device__ float g_v[BATCH*SEQ*DIM];
__device__ float g_pe[R2*DIM];
__device__ float g_E[R2*DIM];
__device__ float g_att[BATCH*SEQ*DIM];

// ---------------- relative sinusoidal PE (all-float: no fp64 pipe) --------
__global__ void pe_kernel(float* __restrict__ pe) {
    int i = blockIdx.x;           // 0..2046
    int j = threadIdx.x;          // 0..255
    float pos  = (float)(SEQ - 1 - i);
    // ln(10000)/256
    float invf = expf(-(float)j * 0.03597789207803197f);
    float ang  = pos * invf;
    float s, c;
    sincosf(ang, &s, &c);
    pe[(size_t)i*DIM + 2*j]     = s;
    pe[(size_t)i*DIM + 2*j + 1] = c;
}

// ---------------- 128x128x16 NT gemm body (C = A @ W^T + bias) ------------
#define GBM 128
#define GBN 128
#define GBK 16

__device__ __forceinline__
void gemm128_body(const float* __restrict__ A, const float* __restrict__ W,
                  const float* __restrict__ bias, float* __restrict__ C, int M) {
    __shared__ float sA[GBK][GBM + 4];
    __shared__ float sB[GBK][GBN + 4];
    const int tid = threadIdx.x;
    const int tx  = tid & 15;
    const int ty  = tid >> 4;
    const int m0  = blockIdx.y * GBM;
    const int n0  = blockIdx.x * GBN;
    const int lr  = tid >> 2;          // 0..63
    const int lc  = (tid & 3) * 4;     // 0,4,8,12

    float acc[8][8];
    #pragma unroll
    for (int i = 0; i < 8; i++)
        #pragma unroll
        for (int j = 0; j < 8; j++) acc[i][j] = 0.f;

    for (int k0 = 0; k0 < DIM; k0 += GBK) {
        #pragma unroll
        for (int half = 0; half < 2; half++) {
            int mr = lr + half * 64;
            int m  = m0 + mr;
            float4 va = make_float4(0.f, 0.f, 0.f, 0.f);
            if (m < M) va = *(const float4*)(A + (size_t)m*DIM + k0 + lc);
            sA[lc+0][mr] = va.x; sA[lc+1][mr] = va.y;
            sA[lc+2][mr] = va.z; sA[lc+3][mr] = va.w;
            int n = n0 + mr;   // N = 512 always exact
            float4 vb = *(const float4*)(W + (size_t)n*DIM + k0 + lc);
            sB[lc+0][mr] = vb.x; sB[lc+1][mr] = vb.y;
            sB[lc+2][mr] = vb.z; sB[lc+3][mr] = vb.w;
        }
        __syncthreads();
        #pragma unroll
        for (int kk = 0; kk < GBK; kk++) {
            float ra[8], rb[8];
            *(float4*)(ra)     = *(float4*)&sA[kk][ty*8];
            *(float4*)(ra + 4) = *(float4*)&sA[kk][ty*8 + 4];
            *(float4*)(rb)     = *(float4*)&sB[kk][tx*8];
            *(float4*)(rb + 4) = *(float4*)&sB[kk][tx*8 + 4];
            #pragma unroll
            for (int i = 0; i < 8; i++)
                #pragma unroll
                for (int j = 0; j < 8; j++)
                    acc[i][j] += ra[i] * rb[j];
        }
        __syncthreads();
    }
    #pragma unroll
    for (int i = 0; i < 8; i++) {
        int m = m0 + ty*8 + i;
        if (m >= M) continue;
        #pragma unroll
        for (int jv = 0; jv < 2; jv++) {
            int n = n0 + tx*8 + jv*4;
            float4 bb = *(const float4*)(bias + n);
            float4 o;
            o.x = acc[i][jv*4+0] + bb.x;
            o.y = acc[i][jv*4+1] + bb.y;
            o.z = acc[i][jv*4+2] + bb.z;
            o.w = acc[i][jv*4+3] + bb.w;
            *(float4*)(C + (size_t)m*DIM + n) = o;
        }
    }
}

// Fused Q/K/V/E projections: z selects the operand set. Grid (4, 32, 4);
// z==3 (E, M=2047 -> 16 y-tiles) masks y>=16.
__global__ __launch_bounds__(256, 2)
void proj_fused(const float* __restrict__ q_in, const float* __restrict__ k_in,
                const float* __restrict__ v_in, const float* __restrict__ pe_in,
                const float* __restrict__ Wq, const float* __restrict__ bq,
                const float* __restrict__ Wk, const float* __restrict__ bk,
                const float* __restrict__ Wv, const float* __restrict__ bv,
                const float* __restrict__ Wp, const float* __restrict__ bp,
                float* __restrict__ oq, float* __restrict__ ok,
                float* __restrict__ ov, float* __restrict__ oE) {
    int z = blockIdx.z;
    const float *A, *W, *b; float* C; int M;
    if (z == 0)      { A = q_in;  W = Wq; b = bq; C = oq; M = BATCH*SEQ; }
    else if (z == 1) { A = k_in;  W = Wk; b = bk; C = ok; M = BATCH*SEQ; }
    else if (z == 2) { A = v_in;  W = Wv; b = bv; C = ov; M = BATCH*SEQ; }
    else             { A = pe_in; W = Wp; b = bp; C = oE; M = R2;
                       if (blockIdx.y >= 16) return; }
    gemm128_body(A, W, b, C, M);
}

// ---------------- 64x128x16 NT gemm (for the dependent output GEMM) -------
__global__ __launch_bounds__(256, 3)
void gemm64_nt_bias(const float* __restrict__ A, const float* __restrict__ W,
                    const float* __restrict__ bias, float* __restrict__ C, int M) {
    __shared__ float sA[16][68];
    __shared__ float sB[16][132];
    const int tid = threadIdx.x;
    const int tx  = tid & 15;     // 8 cols each
    const int ty  = tid >> 4;     // 4 rows each
    const int m0  = blockIdx.y * 64;
    const int n0  = blockIdx.x * 128;
    const int lr  = tid >> 2;     // 0..63
    const int lc  = (tid & 3) * 4;

    float acc[4][8];
    #pragma unroll
    for (int i = 0; i < 4; i++)
        #pragma unroll
        for (int j = 0; j < 8; j++) acc[i][j] = 0.f;

    for (int k0 = 0; k0 < DIM; k0 += 16) {
        {
            int m = m0 + lr;
            float4 va = make_float4(0.f, 0.f, 0.f, 0.f);
            if (m < M) va = *(const float4*)(A + (size_t)m*DIM + k0 + lc);
            sA[lc+0][lr] = va.x; sA[lc+1][lr] = va.y;
            sA[lc+2][lr] = va.z; sA[lc+3][lr] = va.w;
        }
        #pragma unroll
        for (int half = 0; half < 2; half++) {
            int nr = lr + half*64;
            float4 vb = *(const float4*)(W + (size_t)(n0+nr)*DIM + k0 + lc);
            sB[lc+0][nr] = vb.x; sB[lc+1][nr] = vb.y;
            sB[lc+2][nr] = vb.z; sB[lc+3][nr] = vb.w;
        }
        __syncthreads();
        #pragma unroll
        for (int kk = 0; kk < 16; kk++) {
            float ra[4], rb[8];
            *(float4*)ra       = *(float4*)&sA[kk][ty*4];
            *(float4*)(rb)     = *(float4*)&sB[kk][tx*8];
            *(float4*)(rb + 4) = *(float4*)&sB[kk][tx*8 + 4];
            #pragma unroll
            for (int i = 0; i < 4; i++)
                #pragma unroll
                for (int j = 0; j < 8; j++)
                    acc[i][j] += ra[i] * rb[j];
        }
        __syncthreads();
    }
    #pragma unroll
    for (int i = 0; i < 4; i++) {
        int m = m0 + ty*4 + i;
        if (m >= M) continue;
        #pragma unroll
        for (int jv = 0; jv < 2; jv++) {
            int n = n0 + tx*8 + jv*4;
            float4 bb = *(const float4*)(bias + n);
            float4 o;
            o.x = acc[i][jv*4+0] + bb.x;
            o.y = acc[i][jv*4+1] + bb.y;
            o.z = acc[i][jv*4+2] + bb.z;
            o.w = acc[i][jv*4+3] + bb.w;
            *(float4*)(C + (size_t)m*DIM + n) = o;
        }
    }
}

// ---------------- fused rel-pos flash attention ----------------
// One block = (b,h, 64-row q-tile). 8 k-tiles of 128.
// S[qi,kj] = (Qu.K + Qv.E[band shift]) / 8, online softmax, O += P.V
// E band rows per tile pair: 191 (= 64+128-1), row 191 zero pad.
#define KT   128
#define BAND 191
#define ESTR 196   // 192 + 4 pad
#define ATTN_SMEM_FLOATS (2*64*68 + 64*132 + 128*68 + 2*64*196 + 4*64 + 64*16)
#define ATTN_SMEM_BYTES  (ATTN_SMEM_FLOATS * 4)

__global__ __launch_bounds__(256, 1)
void attn_kernel(const float* __restrict__ gq, const float* __restrict__ gk,
                 const float* __restrict__ gv, const float* __restrict__ gE,
                 const float* __restrict__ ub, const float* __restrict__ vb,
                 float* __restrict__ gatt) {
    extern __shared__ float sm[];
    float* sQuT = sm;                 // [64 d][68]
    float* sQvT = sQuT + 64*68;       // [64 d][68]
    float* sKT  = sQvT + 64*68;       // [64 d][132]  (kj 0..127)
    float* sV   = sKT  + 64*132;      // [128 kj][68]
    float* sEt  = sV   + 128*68;      // [64 d][196]  (t 0..191)
    float* sT2  = sEt  + 64*196;      // [64 qi][196]; sP aliases (stride 132)
    float* sP   = sT2;                // alias: T2 dead once S computed
    float* m_run    = sT2 + 64*196;   // [64]
    float* l_run    = m_run + 64;
    float* rowscale = l_run + 64;
    float* msub     = rowscale + 64;
    float* red      = msub + 64;      // [64][16]

    const int tid = threadIdx.x;
    const int tx  = tid & 15;
    const int ty  = tid >> 4;
    const int b   = blockIdx.y >> 3;
    const int h   = blockIdx.y & 7;
    const int q0  = blockIdx.x * 64;
    const size_t headoff = (size_t)h * DHD;

    // ---- load Qu/Qv (transposed, bias fused) ----
    #pragma unroll
    for (int it = 0; it < 4; it++) {
        int idx = tid + it*256;
        int row = idx >> 4;
        int c4  = (idx & 15) * 4;
        float4 val = *(const float4*)(gq + ((size_t)(b*SEQ) + q0 + row)*DIM + headoff + c4);
        float4 u4  = *(const float4*)(ub + headoff + c4);
        float4 v4  = *(const float4*)(vb + headoff + c4);
        sQuT[(c4+0)*68+row] = val.x + u4.x;
        sQuT[(c4+1)*68+row] = val.y + u4.y;
        sQuT[(c4+2)*68+row] = val.z + u4.z;
        sQuT[(c4+3)*68+row] = val.w + u4.w;
        sQvT[(c4+0)*68+row] = val.x + v4.x;
        sQvT[(c4+1)*68+row] = val.y + v4.y;
        sQvT[(c4+2)*68+row] = val.z + v4.z;
        sQvT[(c4+3)*68+row] = val.w + v4.w;
    }
    if (tid < 64) { m_run[tid] = -INFINITY; l_run[tid] = 0.f; }
    float accO[4][4];
    #pragma unroll
    for (int i = 0; i < 4; i++)
        #pragma unroll
        for (int j = 0; j < 4; j++) accO[i][j] = 0.f;
    __syncthreads();

    for (int kt = 0; kt < 8; kt++) {
        const int k0 = kt * KT;
        // ---- load K (transposed) and V (row-major): 128 rows x 64 d ----
        #pragma unroll
        for (int it = 0; it < 8; it++) {
            int idx = tid + it*256;
            int row = idx >> 4;            // 0..127
            int c4  = (idx & 15) * 4;
            float4 kvv = *(const float4*)(gk + ((size_t)(b*SEQ) + k0 + row)*DIM + headoff + c4);
            sKT[(c4+0)*132+row] = kvv.x; sKT[(c4+1)*132+row] = kvv.y;
            sKT[(c4+2)*132+row] = kvv.z; sKT[(c4+3)*132+row] = kvv.w;
            float4 vvv = *(const float4*)(gv + ((size_t)(b*SEQ) + k0 + row)*DIM + headoff + c4);
            *(float4*)&sV[row*68 + c4] = vvv;
        }
        // ---- load E band rows [rbase, rbase+190] (transposed); row 191 zero ----
        const int rbase = k0 - q0 + (SEQ - 64);
        #pragma unroll
        for (int it = 0; it < 12; it++) {
            int idx  = tid + it*256;
            int trow = idx >> 4;           // 0..191
            int c4   = (idx & 15) * 4;
            float4 ev = make_float4(0.f, 0.f, 0.f, 0.f);
            if (trow < BAND)
                ev = *(const float4*)(gE + (size_t)(rbase + trow)*DIM + headoff + c4);
            sEt[(c4+0)*ESTR+trow] = ev.x; sEt[(c4+1)*ESTR+trow] = ev.y;
            sEt[(c4+2)*ESTR+trow] = ev.z; sEt[(c4+3)*ESTR+trow] = ev.w;
        }
        __syncthreads();

        // ---- T2 = Qv_tile @ E_band^T  (64 x 192), microtile 4x12 ----
        {
            float acc2[4][12];
            #pragma unroll
            for (int i = 0; i < 4; i++)
                #pragma unroll
                for (int j = 0; j < 12; j++) acc2[i][j] = 0.f;
            #pragma unroll 4
            for (int d = 0; d < 64; d++) {
                float a[4], e[12];
                *(float4*)a     = *(float4*)&sQvT[d*68 + ty*4];
                *(float4*)(e)   = *(float4*)&sEt[d*ESTR + tx*12];
                *(float4*)(e+4) = *(float4*)&sEt[d*ESTR + tx*12 + 4];
                *(float4*)(e+8) = *(float4*)&sEt[d*ESTR + tx*12 + 8];
                #pragma unroll
                for (int i = 0; i < 4; i++)
                    #pragma unroll
                    for (int j = 0; j < 12; j++)
                        acc2[i][j] += a[i] * e[j];
            }
            #pragma unroll
            for (int i = 0; i < 4; i++) {
                *(float4*)&sT2[(ty*4+i)*ESTR + tx*12]     = *(float4*)&acc2[i][0];
                *(float4*)&sT2[(ty*4+i)*ESTR + tx*12 + 4] = *(float4*)&acc2[i][4];
                *(float4*)&sT2[(ty*4+i)*ESTR + tx*12 + 8] = *(float4*)&acc2[i][8];
            }
        }
        __syncthreads();

        // ---- S = Qu.K^T + shift(T2), scaled; microtile 4x8 ----
        float S[4][8];
        {
            float acc1[4][8];
            #pragma unroll
            for (int i = 0; i < 4; i++)
                #pragma unroll
                for (int j = 0; j < 8; j++) acc1[i][j] = 0.f;
            #pragma unroll 8
            for (int d = 0; d < 64; d++) {
                float a[4], kk_[8];
                *(float4*)a        = *(float4*)&sQuT[d*68 + ty*4];
                *(float4*)(kk_)    = *(float4*)&sKT[d*132 + tx*8];
                *(float4*)(kk_+4)  = *(float4*)&sKT[d*132 + tx*8 + 4];
                #pragma unroll
                for (int i = 0; i < 4; i++)
                    #pragma unroll
                    for (int j = 0; j < 8; j++)
                        acc1[i][j] += a[i] * kk_[j];
            }
            #pragma unroll
            for (int i = 0; i < 4; i++)
                #pragma unroll
                for (int j = 0; j < 8; j++) {
                    int t = (tx*8 + j) - (ty*4 + i) + 63;   // 0..190
                    S[i][j] = (acc1[i][j] + sT2[(ty*4+i)*ESTR + t]) * 0.125f;
                }
        }

        // ---- online softmax ----
        #pragma unroll
        for (int i = 0; i < 4; i++) {
            float pm = S[i][0];
            #pragma unroll
            for (int j = 1; j < 8; j++) pm = fmaxf(pm, S[i][j]);
            red[(ty*4+i)*16 + tx] = pm;
        }
        __syncthreads();
        if (tid < 64) {
            float tm = red[tid*16];
            #pragma unroll
            for (int c2 = 1; c2 < 16; c2++) tm = fmaxf(tm, red[tid*16 + c2]);
            float mold = m_run[tid];
            float mn   = fmaxf(mold, tm);
            float rs   = (mold == -INFINITY) ? 0.f : __expf(mold - mn);
            rowscale[tid] = rs;
            msub[tid]     = mn;
            m_run[tid]    = mn;
            l_run[tid]   *= rs;
        }
        __syncthreads();
        // P write (sP aliases sT2 — safe: sync above separates last T2 read)
        #pragma unroll
        for (int i = 0; i < 4; i++) {
            int row  = ty*4 + i;
            float mn = msub[row];
            float rs = rowscale[row];
            float ps = 0.f;
            float pv[8];
            #pragma unroll
            for (int j = 0; j < 8; j++) {
                float p = __expf(S[i][j] - mn);
                pv[j] = p;
                ps += p;
            }
            *(float4*)&sP[row*132 + tx*8]     = *(float4*)&pv[0];
            *(float4*)&sP[row*132 + tx*8 + 4] = *(float4*)&pv[4];
            #pragma unroll
            for (int j = 0; j < 4; j++) accO[i][j] *= rs;
            red[row*16 + tx] = ps;
        }
        __syncthreads();
        if (tid < 64) {
            float ssum = 0.f;
            #pragma unroll
            for (int c2 = 0; c2 < 16; c2++) ssum += red[tid*16 + c2];
            l_run[tid] += ssum;
        }

        // ---- O += P @ V  (O cols = 64 -> 4 per thread) ----
        #pragma unroll 8
        for (int kj = 0; kj < KT; kj++) {
            float vv[4];
            *(float4*)vv = *(float4*)&sV[kj*68 + tx*4];
            #pragma unroll
            for (int i = 0; i < 4; i++) {
                float p = sP[(ty*4+i)*132 + kj];
                #pragma unroll
                for (int j = 0; j < 4; j++)
                    accO[i][j] += p * vv[j];
            }
        }
        __syncthreads();
    }

    // ---- normalize + store ----
    #pragma unroll
    for (int i = 0; i < 4; i++) {
        int row = ty*4 + i;
        float inv = 1.f / l_run[row];
        float4 o;
        o.x = accO[i][0]*inv; o.y = accO[i][1]*inv;
        o.z = accO[i][2]*inv; o.w = accO[i][3]*inv;
        *(float4*)(gatt + ((size_t)(b*SEQ) + q0 + row)*DIM + headoff + tx*4) = o;
    }
}

// ---------------- launcher ----------------
extern "C" void kernel_launch(void* const* d_in, const int* in_sizes, int n_in,
                              void* d_out, int out_size) {
    const float* query  = (const float*)d_in[0];
    const float* key_   = (const float*)d_in[1];
    const float* value  = (const float*)d_in[2];
    const float* Wq     = (const float*)d_in[3];
    const float* bq     = (const float*)d_in[4];
    const float* Wk     = (const float*)d_in[5];
    const float* bk     = (const float*)d_in[6];
    const float* Wv     = (const float*)d_in[7];
    const float* bv     = (const float*)d_in[8];
    const float* Wp     = (const float*)d_in[9];
    const float* bp     = (const float*)d_in[10];
    const float* Wo     = (const float*)d_in[11];
    const float* bo     = (const float*)d_in[12];
    const float* u_bias = (const float*)d_in[13];
    const float* v_bias = (const float*)d_in[14];
    float* out = (float*)d_out;

    float *pq, *pk, *pv, *ppe, *pE, *patt;
    cudaGetSymbolAddress((void**)&pq,   g_q);
    cudaGetSymbolAddress((void**)&pk,   g_k);
    cudaGetSymbolAddress((void**)&pv,   g_v);
    cudaGetSymbolAddress((void**)&ppe,  g_pe);
    cudaGetSymbolAddress((void**)&pE,   g_E);
    cudaGetSymbolAddress((void**)&patt, g_att);

    cudaFuncSetAttribute(attn_kernel, cudaFuncAttributeMaxDynamicSharedMemorySize,
                         ATTN_SMEM_BYTES);

    pe_kernel<<<R2, 256>>>(ppe);
    proj_fused<<<dim3(4, 32, 4), 256>>>(query, key_, value, ppe,
                                        Wq, bq, Wk, bk, Wv, bv, Wp, bp,
                                        pq, pk, pv, pE);
    attn_kernel<<<dim3(16, 32), 256, ATTN_SMEM_BYTES>>>(pq, pk, pv, pE,
                                                        u_bias, v_bias, patt);
    gemm64_nt_bias<<<dim3(4, 64), 256>>>(patt, Wo, bo, out, BATCH*SEQ);
}